// round 12
// baseline (speedup 1.0000x reference)
#include <cuda_runtime.h>
#include <cuda_fp16.h>
#include <cstdint>
#include <cstddef>

// ---------------- problem constants ----------------
#define MTOK   8192            // Bt*S tokens
#define DIN    4096
#define DOUT   4096
#define NEXP   8
#define DK     32
#define RK     16
#define KLORA  (NEXP*RK)       // 128
#define KEXT   (DIN + KLORA)   // 4224
#define NROUT  (NEXP*DK*2 + KLORA)  // 640 = 256 q + 256 k + 128 h
#define SCALING 1.0f

// ---------------- device scratch (static, no allocs allowed) ----------------
__device__ __align__(1024) __half g_xh[(size_t)MTOK * KEXT];
__device__ __align__(1024) __half g_wh[(size_t)DOUT * KEXT];
__device__ __align__(1024) __half g_rh[(size_t)NROUT * DIN];
__device__ __align__(1024) float  g_P [(size_t)MTOK * NROUT];   // split-K half 0
__device__ __align__(1024) float  g_P2[(size_t)MTOK * NROUT];   // split-K half 1

// ---------------- small helpers ----------------
#define DEVFN __device__ __forceinline__

#define SMEM_SWZ(o) ((o) ^ (((o) >> 3) & 0x70))

DEVFN uint32_t smem_u32(const void* p) {
    uint32_t a;
    asm("{ .reg .u64 t; cvta.to.shared.u64 t, %1; cvt.u32.u64 %0, t; }"
        : "=r"(a) : "l"(p));
    return a;
}

DEVFN void cp16(uint32_t s, const void* g) {
    asm volatile("cp.async.cg.shared.global [%0], [%1], 16;" :: "r"(s), "l"(g));
}
DEVFN void cp_commit() { asm volatile("cp.async.commit_group;" ::: "memory"); }
DEVFN void cp_wait1()  { asm volatile("cp.async.wait_group 1;"  ::: "memory"); }
DEVFN void cp_wait2()  { asm volatile("cp.async.wait_group 2;"  ::: "memory"); }

DEVFN void ldsm4(uint32_t* r, uint32_t a) {
    asm volatile("ldmatrix.sync.aligned.m8n8.x4.shared.b16 {%0,%1,%2,%3}, [%4];"
                 : "=r"(r[0]), "=r"(r[1]), "=r"(r[2]), "=r"(r[3]) : "r"(a));
}

DEVFN void mma16816(float* c, const uint32_t* a, const uint32_t* b) {
    asm volatile(
        "mma.sync.aligned.m16n8k16.row.col.f32.f16.f16.f32 "
        "{%0,%1,%2,%3}, {%4,%5,%6,%7}, {%8,%9}, {%0,%1,%2,%3};"
        : "+f"(c[0]), "+f"(c[1]), "+f"(c[2]), "+f"(c[3])
        : "r"(a[0]), "r"(a[1]), "r"(a[2]), "r"(a[3]), "r"(b[0]), "r"(b[1]));
}

DEVFN void cvt8_store(void* dst, float4 v0, float4 v1) {
    __half2 h[4];
    h[0] = __float22half2_rn(make_float2(v0.x, v0.y));
    h[1] = __float22half2_rn(make_float2(v0.z, v0.w));
    h[2] = __float22half2_rn(make_float2(v1.x, v1.y));
    h[3] = __float22half2_rn(make_float2(v1.z, v1.w));
    *(uint4*)dst = *(uint4*)h;
}

// ---------------- merged conversion kernel (fp32 -> fp16, 8 elems/thread) -------
#define NG_X  ((size_t)MTOK * DIN / 8)     // 4194304
#define NG_W  ((size_t)DOUT * DIN / 8)     // 2097152
#define NG_R  ((size_t)NROUT * DIN / 8)    // 327680
#define NG_BM ((size_t)DOUT * KLORA / 8)   // 65536
#define CONV_BLOCKS ((NG_X + NG_W + NG_R + NG_BM) / 256)

__global__ void conv_all(const float* __restrict__ x, const float* __restrict__ W,
                         const float* __restrict__ Bm, const float* __restrict__ Wq,
                         const float* __restrict__ Wk, const float* __restrict__ A) {
    size_t gi = (size_t)blockIdx.x * 256 + threadIdx.x;
    if (gi < NG_X) {
        const float4* s = (const float4*)x + gi * 2;
        float4 v0 = s[0], v1 = s[1];
        size_t m = gi >> 9, c = (gi & 511) * 8;        // DIN/8 = 512
        cvt8_store(&g_xh[m * KEXT + c], v0, v1);
        return;
    }
    gi -= NG_X;
    if (gi < NG_W) {
        const float4* s = (const float4*)W + gi * 2;
        float4 v0 = s[0], v1 = s[1];
        size_t o = gi >> 9, c = (gi & 511) * 8;
        cvt8_store(&g_wh[o * KEXT + c], v0, v1);
        return;
    }
    gi -= NG_W;
    if (gi < NG_R) {
        size_t row = gi >> 9, c = (gi & 511) * 8;
        const float* src = (row < 256) ? (Wq + row * DIN)
                        : (row < 512) ? (Wk + (row - 256) * DIN)
                                      : (A  + (row - 512) * DIN);
        const float4* s = (const float4*)(src + c);
        cvt8_store(&g_rh[row * DIN + c], s[0], s[1]);
        return;
    }
    gi -= NG_R;
    {
        size_t o = gi >> 4;
        int t0 = (int)(gi & 15) * 8;
        int e = t0 >> 4, r0 = t0 & 15;
        const float4* s = (const float4*)(Bm + ((size_t)e * DOUT + o) * RK + r0);
        cvt8_store(&g_wh[o * KEXT + DIN + t0], s[0], s[1]);
    }
}

// ---------------- routing softmax + hw pack (sums split-K halves) ----------------
__global__ void route_kernel() {
    int wid = threadIdx.x >> 5, lane = threadIdx.x & 31;
    int m = blockIdx.x * 8 + wid;
    const float* r0 = g_P  + (size_t)m * NROUT;
    const float* r1 = g_P2 + (size_t)m * NROUT;
    float s[NEXP];
#pragma unroll
    for (int e = 0; e < NEXP; e++) {
        int iq = e * 32 + lane, ik = 256 + e * 32 + lane;
        float q = r0[iq] + r1[iq];
        float k = r0[ik] + r1[ik];
        float p = q * k;
#pragma unroll
        for (int off = 16; off; off >>= 1) p += __shfl_xor_sync(0xffffffffu, p, off);
        s[e] = p * 0.17677669529663687f;   // 1/sqrt(32)
    }
    float mx = s[0];
#pragma unroll
    for (int e = 1; e < NEXP; e++) mx = fmaxf(mx, s[e]);
    float w[NEXP], den = 0.f;
#pragma unroll
    for (int e = 0; e < NEXP; e++) { w[e] = expf(s[e] - mx); den += w[e]; }
    float inv = SCALING / den;
#pragma unroll
    for (int t = lane; t < KLORA; t += 32) {
        int e = t >> 4;
        float h = r0[512 + t] + r1[512 + t];
        float hw = w[e] * inv * h;
        g_xh[(size_t)m * KEXT + DIN + t] = __float2half(hw);
    }
}

// ---------------- routing GEMM: templated fp16 mma.sync (BM x 128 tile) ----------
#define STAGES 3

template<int BM, int WMW>
__global__ __launch_bounds__(256, 2) void gemm_t(
        const __half* __restrict__ Amat, const __half* __restrict__ Bmat,
        int lda, int ldb, int ldc, int kchunks,
        float* __restrict__ C, const float* __restrict__ bias,
        size_t csplit) {
    constexpr int WNW = 8 / WMW;
    constexpr int WN  = 128 / WNW;
    constexpr int NI  = WN / 8;
    constexpr int STAGE_BYTES = (BM + 128) * 128;

    extern __shared__ char smem[];
    const uint32_t sb = smem_u32(smem);
    const int tid = threadIdx.x, wid = tid >> 5, lid = tid & 31;

    const int n0 = blockIdx.x * 128, m0 = blockIdx.y * BM;
    const size_t koff = (size_t)blockIdx.z * kchunks * 64;
    C += (size_t)blockIdx.z * csplit;

    const char* pA = (const char*)(Amat + (size_t)m0 * lda + koff);
    const char* pB = (const char*)(Bmat + (size_t)n0 * ldb + koff);
    const size_t la = (size_t)lda * 2, lb = (size_t)ldb * 2;

    auto issue_stage = [&](int ck, int stage) {
        const size_t kb = (size_t)ck * 128;
        const uint32_t sbase = sb + (uint32_t)stage * STAGE_BYTES;
#pragma unroll
        for (int i = 0; i < BM * 8 / 256; i++) {
            int s = tid + i * 256;
            int r = s >> 3, c = (s & 7) * 16;
            uint32_t so = SMEM_SWZ((uint32_t)(r * 128 + c));
            cp16(sbase + so, pA + (size_t)r * la + kb + c);
        }
#pragma unroll
        for (int i = 0; i < 4; i++) {
            int s = tid + i * 256;
            int r = s >> 3, c = (s & 7) * 16;
            uint32_t so = SMEM_SWZ((uint32_t)(r * 128 + c));
            cp16(sbase + (uint32_t)(BM * 128) + so, pB + (size_t)r * lb + kb + c);
        }
    };

    const int warp_m = wid & (WMW - 1), warp_n = wid / WMW;

    float acc[2][NI][4];
#pragma unroll
    for (int a = 0; a < 2; a++)
#pragma unroll
        for (int b = 0; b < NI; b++)
#pragma unroll
            for (int c = 0; c < 4; c++) acc[a][b][c] = 0.f;

    issue_stage(0, 0); cp_commit();
    issue_stage(1, 1); cp_commit();

    const int a_row = warp_m * 32 + (lid & 15);
    const int a_kh2 = ((lid >> 4) << 3) * 2;
    const int b_row = warp_n * WN + (lid & 7);
    const int b_kh2 = ((((lid >> 3) & 1) << 3)) * 2;
    const int b_nb  = (lid >> 4);
    const uint32_t xa = (uint32_t)((a_row & 7) * 16);
    const uint32_t xb = (uint32_t)((b_row & 7) * 16);
    uint32_t aR[2], bR[NI / 2];
#pragma unroll
    for (int mi = 0; mi < 2; mi++) aR[mi] = (uint32_t)((a_row + mi * 16) * 128);
#pragma unroll
    for (int nj = 0; nj < NI / 2; nj++)
        bR[nj] = (uint32_t)((b_row + (nj * 2 + b_nb) * 8) * 128);

    int rstage = 0, wstage = 2;
    for (int ck = 0; ck < kchunks; ck++) {
        cp_wait1();
        __syncthreads();
        if (ck + 2 < kchunks) issue_stage(ck + 2, wstage);
        cp_commit();
        if (++wstage == STAGES) wstage = 0;

        const uint32_t sA = sb + (uint32_t)rstage * STAGE_BYTES;
        const uint32_t sB = sA + (uint32_t)(BM * 128);
        if (++rstage == STAGES) rstage = 0;

#pragma unroll
        for (int kk = 0; kk < 64; kk += 16) {
            const uint32_t ca = (uint32_t)(kk * 2 + a_kh2) ^ xa;
            const uint32_t cb = (uint32_t)(kk * 2 + b_kh2) ^ xb;
            uint32_t Af[2][4], Bf[NI][2];
#pragma unroll
            for (int mi = 0; mi < 2; mi++) ldsm4(Af[mi], sA + aR[mi] + ca);
#pragma unroll
            for (int nj = 0; nj < NI / 2; nj++) {
                uint32_t t[4];
                ldsm4(t, sB + bR[nj] + cb);
                Bf[nj * 2][0]     = t[0]; Bf[nj * 2][1]     = t[1];
                Bf[nj * 2 + 1][0] = t[2]; Bf[nj * 2 + 1][1] = t[3];
            }
#pragma unroll
            for (int mi = 0; mi < 2; mi++)
#pragma unroll
                for (int ni = 0; ni < NI; ni++) mma16816(acc[mi][ni], Af[mi], Bf[ni]);
        }
    }

    const int gr = lid >> 2, c0 = (lid & 3) * 2;
    const bool use_bias = (bias != nullptr);
#pragma unroll
    for (int mi = 0; mi < 2; mi++) {
        int row = m0 + warp_m * 32 + mi * 16 + gr;
#pragma unroll
        for (int ni = 0; ni < NI; ni++) {
            int col = n0 + warp_n * WN + ni * 8 + c0;
            float b0 = use_bias ? bias[col]     : 0.f;
            float b1 = use_bias ? bias[col + 1] : 0.f;
            float2 v0 = make_float2(acc[mi][ni][0] + b0, acc[mi][ni][1] + b1);
            float2 v1 = make_float2(acc[mi][ni][2] + b0, acc[mi][ni][3] + b1);
            *(float2*)&C[(size_t)row * ldc + col]       = v0;
            *(float2*)&C[(size_t)(row + 8) * ldc + col] = v1;
        }
    }
}

// ---------------- MAIN GEMM: 128x256 CTA tile, 64x64 warp tiles, 4-stage -------
// out[8192,4096] = [x|hw] @ [W|Bm]^T + b, K = KEXT = 4224. All strides constexpr.
#define MSTAGES     4
#define MSTAGE_B    ((128 + 256) * 128)          // 49152 bytes per stage
#define SMEM_MAIN   (MSTAGES * MSTAGE_B)         // 196608 = 192 KB
#define MKCH        (KEXT / 64)                  // 66 chunks
#define ROW_STEP    ((size_t)32 * KEXT * 2)      // gmem bytes per 32 rows

__global__ __launch_bounds__(256, 1) void gemm_main(float* __restrict__ C,
                                                    const float* __restrict__ bias) {
    extern __shared__ char smem[];
    const uint32_t sb = smem_u32(smem);
    const int tid = threadIdx.x, wid = tid >> 5, lid = tid & 31;

    const int n0 = blockIdx.x * 256, m0 = blockIdx.y * 128;

    // per-thread copy bases: 8 threads/row (8 x 16B = 128B row)
    const char* gA = (const char*)(g_xh + (size_t)(m0 + (tid >> 3)) * KEXT) + (tid & 7) * 16;
    const char* gB = (const char*)(g_wh + (size_t)(n0 + (tid >> 3)) * KEXT) + (tid & 7) * 16;
    const uint32_t sOff = SMEM_SWZ((uint32_t)((tid >> 3) * 128 + (tid & 7) * 16));

    auto issue_stage = [&](int ck, int stage) {
        const size_t kb = (size_t)ck * 128;
        const uint32_t base = sb + (uint32_t)stage * MSTAGE_B + sOff;
#pragma unroll
        for (int i = 0; i < 4; i++)                 // A: 128 rows
            cp16(base + i * 4096u, gA + kb + i * ROW_STEP);
#pragma unroll
        for (int i = 0; i < 8; i++)                 // B: 256 rows
            cp16(base + 16384u + i * 4096u, gB + kb + i * ROW_STEP);
    };

    // 8 warps: 2 along m (64 rows), 4 along n (64 cols)
    const int warp_m = wid & 1, warp_n = wid >> 1;

    float acc[4][8][4];
#pragma unroll
    for (int a = 0; a < 4; a++)
#pragma unroll
        for (int b = 0; b < 8; b++)
#pragma unroll
            for (int c = 0; c < 4; c++) acc[a][b][c] = 0.f;

    issue_stage(0, 0); cp_commit();
    issue_stage(1, 1); cp_commit();
    issue_stage(2, 2); cp_commit();

    // fragment addressing (SWZ(r*128+c) = r*128 + (c ^ ((r&7)*16)))
    const int a_row = warp_m * 64 + (lid & 15);
    const int a_kh2 = ((lid >> 4) << 3) * 2;
    const int b_row = warp_n * 64 + (lid & 7);
    const int b_kh2 = ((((lid >> 3) & 1) << 3)) * 2;
    const int b_nb  = (lid >> 4);
    const uint32_t xa = (uint32_t)((a_row & 7) * 16);
    const uint32_t xb = (uint32_t)((b_row & 7) * 16);
    uint32_t aR[4], bR[4];
#pragma unroll
    for (int mi = 0; mi < 4; mi++) aR[mi] = (uint32_t)((a_row + mi * 16) * 128);
#pragma unroll
    for (int nj = 0; nj < 4; nj++)
        bR[nj] = (uint32_t)((b_row + (nj * 2 + b_nb) * 8) * 128);

    int rstage = 0, wstage = 3;
    for (int ck = 0; ck < MKCH; ck++) {
        cp_wait2();
        __syncthreads();
        if (ck + 3 < MKCH) issue_stage(ck + 3, wstage);
        cp_commit();
        if (++wstage == MSTAGES) wstage = 0;

        const uint32_t sA = sb + (uint32_t)rstage * MSTAGE_B;
        const uint32_t sB = sA + 16384u;
        if (++rstage == MSTAGES) rstage = 0;

#pragma unroll
        for (int kk = 0; kk < 64; kk += 16) {
            const uint32_t ca = (uint32_t)(kk * 2 + a_kh2) ^ xa;
            const uint32_t cb = (uint32_t)(kk * 2 + b_kh2) ^ xb;
            uint32_t Af[4][4], Bf[8][2];
#pragma unroll
            for (int mi = 0; mi < 4; mi++) ldsm4(Af[mi], sA + aR[mi] + ca);
#pragma unroll
            for (int nj = 0; nj < 4; nj++) {
                uint32_t t[4];
                ldsm4(t, sB + bR[nj] + cb);
                Bf[nj * 2][0]     = t[0]; Bf[nj * 2][1]     = t[1];
                Bf[nj * 2 + 1][0] = t[2]; Bf[nj * 2 + 1][1] = t[3];
            }
#pragma unroll
            for (int mi = 0; mi < 4; mi++)
#pragma unroll
                for (int ni = 0; ni < 8; ni++) mma16816(acc[mi][ni], Af[mi], Bf[ni]);
        }
    }

    // epilogue: 64x64 warp tile, float2 stores
    const int gr = lid >> 2, c0 = (lid & 3) * 2;
#pragma unroll
    for (int mi = 0; mi < 4; mi++) {
        int row = m0 + warp_m * 64 + mi * 16 + gr;
#pragma unroll
        for (int ni = 0; ni < 8; ni++) {
            int col = n0 + warp_n * 64 + ni * 8 + c0;
            float b0 = bias[col];
            float b1 = bias[col + 1];
            float2 v0 = make_float2(acc[mi][ni][0] + b0, acc[mi][ni][1] + b1);
            float2 v1 = make_float2(acc[mi][ni][2] + b0, acc[mi][ni][3] + b1);
            *(float2*)&C[(size_t)row * DOUT + col]       = v0;
            *(float2*)&C[(size_t)(row + 8) * DOUT + col] = v1;
        }
    }
}

// ---------------- launch ----------------
extern "C" void kernel_launch(void* const* d_in, const int* in_sizes, int n_in,
                              void* d_out, int out_size) {
    (void)in_sizes; (void)n_in; (void)out_size;
    const float* x  = (const float*)d_in[0];
    const float* W  = (const float*)d_in[1];
    const float* b  = (const float*)d_in[2];
    const float* Wq = (const float*)d_in[3];
    const float* Wk = (const float*)d_in[4];
    const float* A  = (const float*)d_in[5];
    const float* Bm = (const float*)d_in[6];
    float* out = (float*)d_out;

    __half* xh = nullptr; __half* rh = nullptr; float* P = nullptr;
    cudaGetSymbolAddress((void**)&xh, g_xh);
    cudaGetSymbolAddress((void**)&rh, g_rh);
    cudaGetSymbolAddress((void**)&P,  g_P);

    constexpr int SMEM_ROUTE = STAGES * (64 + 128) * 128;   // 72 KB
    cudaFuncSetAttribute(gemm_main, cudaFuncAttributeMaxDynamicSharedMemorySize, SMEM_MAIN);
    cudaFuncSetAttribute(gemm_t<64, 2>, cudaFuncAttributeMaxDynamicSharedMemorySize, SMEM_ROUTE);

    // 1. fp32 -> fp16 conversion/packing (single merged kernel)
    conv_all<<<(unsigned)CONV_BLOCKS, 256>>>(x, W, Bm, Wq, Wk, A);

    // 2. routing GEMM, split-K=2: P[z] = x @ [Wq;Wk;A]^T over K half z
    gemm_t<64, 2><<<dim3(NROUT / 128, MTOK / 64, 2), 256, SMEM_ROUTE>>>(
        xh, rh, KEXT, DIN, NROUT, DIN / 128, P, nullptr, (size_t)MTOK * NROUT);

    // 3. softmax over experts (sums split halves) + pack hw into extended-K cols
    route_kernel<<<MTOK / 8, 256>>>();

    // 4. main fused GEMM: out = [x|hw] @ [W|Bm]^T + b   (8192 x 4096, K=4224)
    gemm_main<<<dim3(DOUT / 256, MTOK / 128), 256, SMEM_MAIN>>>(out, b);
}

// round 14
// speedup vs baseline: 1.0525x; 1.0525x over previous
#include <cuda_runtime.h>
#include <cuda_fp16.h>
#include <cstdint>
#include <cstddef>

// ---------------- problem constants ----------------
#define MTOK   8192            // Bt*S tokens
#define DIN    4096
#define DOUT   4096
#define NEXP   8
#define DK     32
#define RK     16
#define KLORA  (NEXP*RK)       // 128
#define KEXT   (DIN + KLORA)   // 4224
#define NROUT  (NEXP*DK*2 + KLORA)  // 640 = 256 q + 256 k + 128 h
#define NSPLIT 4               // routing GEMM split-K factor
#define SCALING 1.0f

// ---------------- device scratch (static, no allocs allowed) ----------------
__device__ __align__(1024) __half g_xh[(size_t)MTOK * KEXT];
__device__ __align__(1024) __half g_wh[(size_t)DOUT * KEXT];
__device__ __align__(1024) __half g_rh[(size_t)NROUT * DIN];
__device__ __align__(1024) float  g_P [(size_t)NSPLIT * MTOK * NROUT];  // split-K partials

// ---------------- small helpers ----------------
#define DEVFN __device__ __forceinline__

#define SMEM_SWZ(o) ((o) ^ (((o) >> 3) & 0x70))

DEVFN uint32_t smem_u32(const void* p) {
    uint32_t a;
    asm("{ .reg .u64 t; cvta.to.shared.u64 t, %1; cvt.u32.u64 %0, t; }"
        : "=r"(a) : "l"(p));
    return a;
}

DEVFN void cp16(uint32_t s, const void* g) {
    asm volatile("cp.async.cg.shared.global [%0], [%1], 16;" :: "r"(s), "l"(g));
}
DEVFN void cp_commit() { asm volatile("cp.async.commit_group;" ::: "memory"); }
DEVFN void cp_wait1()  { asm volatile("cp.async.wait_group 1;"  ::: "memory"); }

DEVFN void ldsm4(uint32_t* r, uint32_t a) {
    asm volatile("ldmatrix.sync.aligned.m8n8.x4.shared.b16 {%0,%1,%2,%3}, [%4];"
                 : "=r"(r[0]), "=r"(r[1]), "=r"(r[2]), "=r"(r[3]) : "r"(a));
}

DEVFN void mma16816(float* c, const uint32_t* a, const uint32_t* b) {
    asm volatile(
        "mma.sync.aligned.m16n8k16.row.col.f32.f16.f16.f32 "
        "{%0,%1,%2,%3}, {%4,%5,%6,%7}, {%8,%9}, {%0,%1,%2,%3};"
        : "+f"(c[0]), "+f"(c[1]), "+f"(c[2]), "+f"(c[3])
        : "r"(a[0]), "r"(a[1]), "r"(a[2]), "r"(a[3]), "r"(b[0]), "r"(b[1]));
}

DEVFN void cvt8_store(void* dst, float4 v0, float4 v1) {
    __half2 h[4];
    h[0] = __float22half2_rn(make_float2(v0.x, v0.y));
    h[1] = __float22half2_rn(make_float2(v0.z, v0.w));
    h[2] = __float22half2_rn(make_float2(v1.x, v1.y));
    h[3] = __float22half2_rn(make_float2(v1.z, v1.w));
    *(uint4*)dst = *(uint4*)h;
}

// ---------------- conversion kernels (fp32 -> fp16, 8 elems/thread) -------
// conv_xr: x + routing weights (needed by the routing phase)
// conv_wbm: W + Bm (needed only by the main GEMM -> overlapped with routing)
#define NG_X  ((size_t)MTOK * DIN / 8)     // 4194304
#define NG_W  ((size_t)DOUT * DIN / 8)     // 2097152
#define NG_R  ((size_t)NROUT * DIN / 8)    // 327680
#define NG_BM ((size_t)DOUT * KLORA / 8)   // 65536
#define XR_BLOCKS  ((NG_X + NG_R) / 256)
#define WBM_BLOCKS ((NG_W + NG_BM) / 256)

__global__ void conv_xr(const float* __restrict__ x, const float* __restrict__ Wq,
                        const float* __restrict__ Wk, const float* __restrict__ A) {
    size_t gi = (size_t)blockIdx.x * 256 + threadIdx.x;
    if (gi < NG_X) {
        const float4* s = (const float4*)x + gi * 2;
        float4 v0 = s[0], v1 = s[1];
        size_t m = gi >> 9, c = (gi & 511) * 8;        // DIN/8 = 512
        cvt8_store(&g_xh[m * KEXT + c], v0, v1);
        return;
    }
    gi -= NG_X;
    {
        size_t row = gi >> 9, c = (gi & 511) * 8;
        const float* src = (row < 256) ? (Wq + row * DIN)
                        : (row < 512) ? (Wk + (row - 256) * DIN)
                                      : (A  + (row - 512) * DIN);
        const float4* s = (const float4*)(src + c);
        cvt8_store(&g_rh[row * DIN + c], s[0], s[1]);
    }
}

__global__ void conv_wbm(const float* __restrict__ W, const float* __restrict__ Bm) {
    size_t gi = (size_t)blockIdx.x * 256 + threadIdx.x;
    if (gi < NG_W) {
        const float4* s = (const float4*)W + gi * 2;
        float4 v0 = s[0], v1 = s[1];
        size_t o = gi >> 9, c = (gi & 511) * 8;
        cvt8_store(&g_wh[o * KEXT + c], v0, v1);
        return;
    }
    gi -= NG_W;
    {
        size_t o = gi >> 4;
        int t0 = (int)(gi & 15) * 8;
        int e = t0 >> 4, r0 = t0 & 15;
        const float4* s = (const float4*)(Bm + ((size_t)e * DOUT + o) * RK + r0);
        cvt8_store(&g_wh[o * KEXT + DIN + t0], s[0], s[1]);
    }
}

// ---------------- routing softmax + hw pack (sums NSPLIT split-K partials) -------
__global__ void route_kernel() {
    int wid = threadIdx.x >> 5, lane = threadIdx.x & 31;
    int m = blockIdx.x * 8 + wid;
    const size_t S = (size_t)MTOK * NROUT;
    const float* r0 = g_P + (size_t)m * NROUT;
    float s[NEXP];
#pragma unroll
    for (int e = 0; e < NEXP; e++) {
        int iq = e * 32 + lane, ik = 256 + e * 32 + lane;
        float q = 0.f, k = 0.f;
#pragma unroll
        for (int z = 0; z < NSPLIT; z++) { q += r0[iq + z * S]; k += r0[ik + z * S]; }
        float p = q * k;
#pragma unroll
        for (int off = 16; off; off >>= 1) p += __shfl_xor_sync(0xffffffffu, p, off);
        s[e] = p * 0.17677669529663687f;   // 1/sqrt(32)
    }
    float mx = s[0];
#pragma unroll
    for (int e = 1; e < NEXP; e++) mx = fmaxf(mx, s[e]);
    float w[NEXP], den = 0.f;
#pragma unroll
    for (int e = 0; e < NEXP; e++) { w[e] = expf(s[e] - mx); den += w[e]; }
    float inv = SCALING / den;
#pragma unroll
    for (int t = lane; t < KLORA; t += 32) {
        int e = t >> 4;
        float h = 0.f;
#pragma unroll
        for (int z = 0; z < NSPLIT; z++) h += r0[512 + t + z * S];
        float hw = w[e] * inv * h;
        g_xh[(size_t)m * KEXT + DIN + t] = __float2half(hw);
    }
}

// ---------------- fp16 mma.sync GEMM, templated tile (BM x 128, K-chunk 64) ------
// (R11-proven config: 256 threads, 2 CTAs/SM, 3-stage cp.async, hoisted LDSM addrs)
#define STAGES 3

template<int BM, int WMW>
__global__ __launch_bounds__(256, 2) void gemm_t(
        const __half* __restrict__ Amat, const __half* __restrict__ Bmat,
        int lda, int ldb, int ldc, int kchunks,
        float* __restrict__ C, const float* __restrict__ bias,
        size_t csplit) {
    constexpr int WNW = 8 / WMW;
    constexpr int WN  = 128 / WNW;
    constexpr int NI  = WN / 8;
    constexpr int STAGE_BYTES = (BM + 128) * 128;

    extern __shared__ char smem[];
    const uint32_t sb = smem_u32(smem);
    const int tid = threadIdx.x, wid = tid >> 5, lid = tid & 31;

    const int n0 = blockIdx.x * 128, m0 = blockIdx.y * BM;
    const size_t koff = (size_t)blockIdx.z * kchunks * 64;
    C += (size_t)blockIdx.z * csplit;

    const char* pA = (const char*)(Amat + (size_t)m0 * lda + koff);
    const char* pB = (const char*)(Bmat + (size_t)n0 * ldb + koff);
    const size_t la = (size_t)lda * 2, lb = (size_t)ldb * 2;

    auto issue_stage = [&](int ck, int stage) {
        const size_t kb = (size_t)ck * 128;
        const uint32_t sbase = sb + (uint32_t)stage * STAGE_BYTES;
#pragma unroll
        for (int i = 0; i < BM * 8 / 256; i++) {
            int s = tid + i * 256;
            int r = s >> 3, c = (s & 7) * 16;
            uint32_t so = SMEM_SWZ((uint32_t)(r * 128 + c));
            cp16(sbase + so, pA + (size_t)r * la + kb + c);
        }
#pragma unroll
        for (int i = 0; i < 4; i++) {
            int s = tid + i * 256;
            int r = s >> 3, c = (s & 7) * 16;
            uint32_t so = SMEM_SWZ((uint32_t)(r * 128 + c));
            cp16(sbase + (uint32_t)(BM * 128) + so, pB + (size_t)r * lb + kb + c);
        }
    };

    const int warp_m = wid & (WMW - 1), warp_n = wid / WMW;

    float acc[2][NI][4];
#pragma unroll
    for (int a = 0; a < 2; a++)
#pragma unroll
        for (int b = 0; b < NI; b++)
#pragma unroll
            for (int c = 0; c < 4; c++) acc[a][b][c] = 0.f;

    issue_stage(0, 0); cp_commit();
    issue_stage(1, 1); cp_commit();

    const int a_row = warp_m * 32 + (lid & 15);
    const int a_kh2 = ((lid >> 4) << 3) * 2;
    const int b_row = warp_n * WN + (lid & 7);
    const int b_kh2 = ((((lid >> 3) & 1) << 3)) * 2;
    const int b_nb  = (lid >> 4);
    const uint32_t xa = (uint32_t)((a_row & 7) * 16);
    const uint32_t xb = (uint32_t)((b_row & 7) * 16);
    uint32_t aR[2], bR[NI / 2];
#pragma unroll
    for (int mi = 0; mi < 2; mi++) aR[mi] = (uint32_t)((a_row + mi * 16) * 128);
#pragma unroll
    for (int nj = 0; nj < NI / 2; nj++)
        bR[nj] = (uint32_t)((b_row + (nj * 2 + b_nb) * 8) * 128);

    int rstage = 0, wstage = 2;
    for (int ck = 0; ck < kchunks; ck++) {
        cp_wait1();
        __syncthreads();
        if (ck + 2 < kchunks) issue_stage(ck + 2, wstage);
        cp_commit();
        if (++wstage == STAGES) wstage = 0;

        const uint32_t sA = sb + (uint32_t)rstage * STAGE_BYTES;
        const uint32_t sB = sA + (uint32_t)(BM * 128);
        if (++rstage == STAGES) rstage = 0;

#pragma unroll
        for (int kk = 0; kk < 64; kk += 16) {
            const uint32_t ca = (uint32_t)(kk * 2 + a_kh2) ^ xa;
            const uint32_t cb = (uint32_t)(kk * 2 + b_kh2) ^ xb;
            uint32_t Af[2][4], Bf[NI][2];
#pragma unroll
            for (int mi = 0; mi < 2; mi++) ldsm4(Af[mi], sA + aR[mi] + ca);
#pragma unroll
            for (int nj = 0; nj < NI / 2; nj++) {
                uint32_t t[4];
                ldsm4(t, sB + bR[nj] + cb);
                Bf[nj * 2][0]     = t[0]; Bf[nj * 2][1]     = t[1];
                Bf[nj * 2 + 1][0] = t[2]; Bf[nj * 2 + 1][1] = t[3];
            }
#pragma unroll
            for (int mi = 0; mi < 2; mi++)
#pragma unroll
                for (int ni = 0; ni < NI; ni++) mma16816(acc[mi][ni], Af[mi], Bf[ni]);
        }
    }

    const int gr = lid >> 2, c0 = (lid & 3) * 2;
    const bool use_bias = (bias != nullptr);
#pragma unroll
    for (int mi = 0; mi < 2; mi++) {
        int row = m0 + warp_m * 32 + mi * 16 + gr;
#pragma unroll
        for (int ni = 0; ni < NI; ni++) {
            int col = n0 + warp_n * WN + ni * 8 + c0;
            float b0 = use_bias ? bias[col]     : 0.f;
            float b1 = use_bias ? bias[col + 1] : 0.f;
            float2 v0 = make_float2(acc[mi][ni][0] + b0, acc[mi][ni][1] + b1);
            float2 v1 = make_float2(acc[mi][ni][2] + b0, acc[mi][ni][3] + b1);
            *(float2*)&C[(size_t)row * ldc + col]       = v0;
            *(float2*)&C[(size_t)(row + 8) * ldc + col] = v1;
        }
    }
}

// ---------------- launch ----------------
extern "C" void kernel_launch(void* const* d_in, const int* in_sizes, int n_in,
                              void* d_out, int out_size) {
    (void)in_sizes; (void)n_in; (void)out_size;
    const float* x  = (const float*)d_in[0];
    const float* W  = (const float*)d_in[1];
    const float* b  = (const float*)d_in[2];
    const float* Wq = (const float*)d_in[3];
    const float* Wk = (const float*)d_in[4];
    const float* A  = (const float*)d_in[5];
    const float* Bm = (const float*)d_in[6];
    float* out = (float*)d_out;

    __half* xh = nullptr; __half* wh = nullptr; __half* rh = nullptr; float* P = nullptr;
    cudaGetSymbolAddress((void**)&xh, g_xh);
    cudaGetSymbolAddress((void**)&wh, g_wh);
    cudaGetSymbolAddress((void**)&rh, g_rh);
    cudaGetSymbolAddress((void**)&P,  g_P);

    constexpr int SMEM_ROUTE = STAGES * (64 + 128) * 128;   // 72 KB
    constexpr int SMEM_MAIN  = STAGES * (128 + 128) * 128;  // 96 KB
    cudaFuncSetAttribute(gemm_t<64, 2>,  cudaFuncAttributeMaxDynamicSharedMemorySize, SMEM_ROUTE);
    cudaFuncSetAttribute(gemm_t<128, 4>, cudaFuncAttributeMaxDynamicSharedMemorySize, SMEM_MAIN);

    // second stream + fork/join events for overlapping W-conversion with routing.
    // Created fresh each call (graph capture replays don't re-run host code; the
    // handles are intentionally not destroyed during an active capture).
    cudaStream_t s2;
    cudaStreamCreate(&s2);
    cudaEvent_t eFork, eJoin;
    cudaEventCreateWithFlags(&eFork, cudaEventDisableTiming);
    cudaEventCreateWithFlags(&eJoin, cudaEventDisableTiming);

    // 1. convert x + routing weights (critical path)
    conv_xr<<<(unsigned)XR_BLOCKS, 256>>>(x, Wq, Wk, A);

    // fork: W/Bm conversion runs concurrently with the routing phase
    cudaEventRecord(eFork, 0);
    cudaStreamWaitEvent(s2, eFork, 0);
    conv_wbm<<<(unsigned)WBM_BLOCKS, 256, 0, s2>>>(W, Bm);
    cudaEventRecord(eJoin, s2);

    // 2. routing GEMM, split-K=4: P[z] = x @ [Wq;Wk;A]^T over K quarter z
    gemm_t<64, 2><<<dim3(NROUT / 128, MTOK / 64, NSPLIT), 256, SMEM_ROUTE>>>(
        xh, rh, KEXT, DIN, NROUT, DIN / (64 * NSPLIT), P, nullptr,
        (size_t)MTOK * NROUT);

    // 3. softmax over experts (sums partials) + pack hw into extended-K cols
    route_kernel<<<MTOK / 8, 256>>>();

    // join: main GEMM needs g_wh
    cudaStreamWaitEvent(0, eJoin, 0);

    // 4. main fused GEMM: out = [x|hw] @ [W|Bm]^T + b   (8192 x 4096, K=4224)
    gemm_t<128, 4><<<dim3(DOUT / 128, MTOK / 128, 1), 256, SMEM_MAIN>>>(
        xh, wh, KEXT, KEXT, DOUT, KEXT / 64, out, b, 0);
}